// round 14
// baseline (speedup 1.0000x reference)
#include <cuda_runtime.h>
#include <cstdint>

// ---------------------------------------------------------------------------
// Problem constants
// ---------------------------------------------------------------------------
#define L_NUM 2
#define HS    512
#define BB    64
#define SS    1024
#define INW   512
#define ROWS  1024            // 2 gates * HS, interleaved: r = 2*h + g' (g': 0=z, 1=n)
#define SEQ_ELEMS (BB*SS*HS)

// Scan partition: 2 layers x 4 batch-groups (16 b) x 16 row-groups (64 rows)
#define NBG   4
#define GSIZE 16              // CTAs per barrier group
#define WPC   16              // warps per CTA
#define GWARPS (GSIZE*WPC)    // 256 warp-arrivals per group per step

// ---------------------------------------------------------------------------
// Device scratch
// ---------------------------------------------------------------------------
__device__ __align__(16) float g_WG  [L_NUM*ROWS*INW];             // [l][r][i] tf32-rounded
__device__ __align__(16) float g_UG  [L_NUM*ROWS*HS];              // [l][r][o] tf32-rounded
__device__ __align__(16) float g_bias[L_NUM*ROWS];
__device__ __align__(16) float g_Gx  [(size_t)SS*L_NUM*BB*ROWS];   // 512 MB [t][l][b][r]
// H ping-pong, permuted per group block: [p][l][bg][o][ (bl&7)*2 + (bl>>3) ]
__device__ __align__(16) float g_Hbuf[2*L_NUM*NBG*HS*16];
__device__ unsigned long long g_arrive[8*16];                      // 8 counters, 128B apart

__device__ __forceinline__ float rna_tf32(float x) {
    uint32_t r;
    asm("cvt.rna.tf32.f32 %0, %1;" : "=r"(r) : "f"(x));
    return __uint_as_float(r);
}

// D (4xf32) += A (m16k8 tf32, row-major) * B (k8n8 tf32, col-major)
__device__ __forceinline__ void mma_tf32(float* d, const uint32_t* a, const uint32_t* bf) {
    asm volatile(
        "mma.sync.aligned.m16n8k8.row.col.f32.tf32.tf32.f32 "
        "{%0,%1,%2,%3}, {%4,%5,%6,%7}, {%8,%9}, {%0,%1,%2,%3};"
        : "+f"(d[0]), "+f"(d[1]), "+f"(d[2]), "+f"(d[3])
        : "r"(a[0]), "r"(a[1]), "r"(a[2]), "r"(a[3]), "r"(bf[0]), "r"(bf[1]));
}

__device__ __forceinline__ void cp16(void* s, const void* g) {
    uint32_t sa = (uint32_t)__cvta_generic_to_shared(s);
    asm volatile("cp.async.cg.shared.global [%0], [%1], 16;" :: "r"(sa), "l"(g));
}

// ---------------------------------------------------------------------------
// Kernel A: combined weights (tf32-rounded) + biases
// ---------------------------------------------------------------------------
__global__ void combine_kernel(const float* __restrict__ W1, const float* __restrict__ W2,
                               const float* __restrict__ U1, const float* __restrict__ U2,
                               const float* __restrict__ dW1, const float* __restrict__ dW2,
                               const float* __restrict__ dU1, const float* __restrict__ dU2,
                               const float* __restrict__ b1, const float* __restrict__ b2)
{
    int idx = blockIdx.x * blockDim.x + threadIdx.x;   // L*ROWS*INW threads
    int l   = idx >> 19;
    int rem = idx & 524287;
    int r   = rem >> 9;
    int i   = rem & 511;
    int h   = r >> 1;
    int g   = (r & 1) + 1;                             // original gate (1=z, 2=n)

    float w1  = W1 [l*3 + g];
    float dw1 = dW1[l*3 + g];
    float u1  = U1 [l*3 + g];
    float du1 = dU1[l*3 + g];
    int src = (l*HS + h)*INW + i;
    g_WG[idx] = rna_tf32(w1*W2[src] + dw1*dW2[src]);
    g_UG[idx] = rna_tf32(u1*U2[src] + du1*dU2[src]);

    if (idx < L_NUM*ROWS) {
        int ll = idx >> 10;
        int rr = idx & 1023;
        int hh = rr >> 1;
        int gg = (rr & 1) + 1;
        g_bias[idx] = b1[ll*3*HS + gg*HS + hh] + b2[ll*3*HS + gg*HS + hh];
    }
}

// ---------------------------------------------------------------------------
// Init: h0 (L,B,HS) -> permuted Hbuf p=0 block; reset barrier counters
// ---------------------------------------------------------------------------
__global__ void init_h_kernel(const float* __restrict__ h0)
{
    int idx = blockIdx.x * blockDim.x + threadIdx.x;   // 65536 threads
    if (idx < 8*16) g_arrive[idx] = 0ULL;
    int l  = idx >> 15;
    int b  = (idx >> 9) & 63;
    int h  = idx & 511;
    int bg = b >> 4;
    int bl = b & 15;
    size_t blk = ((size_t)(0*L_NUM + l)*NBG + bg) * (HS*16);
    g_Hbuf[blk + h*16 + (bl&7)*2 + (bl>>3)] = h0[idx];
}

// ---------------------------------------------------------------------------
// Kernel B: tf32 mma GEMM with cp.async double buffering (unchanged R13).
//   Gx[t][l][b][r] = sum_i x[b][t][i] * WG[l][r][i]
// ---------------------------------------------------------------------------
#define APITCH 36
#define ABUF   (64*APITCH)
#define BBUF   (128*APITCH)
#define GEMM_SMEM ((2*ABUF + 2*BBUF)*4)   // 55296 B

__global__ void __launch_bounds__(256) gemm_x_kernel(const float* __restrict__ x)
{
    const int t  = blockIdx.x;
    const int rb = blockIdx.y * 128;
    const int l  = blockIdx.z;

    extern __shared__ __align__(16) float smem[];
    float* As = smem;                  // [2][64][36]
    float* Bs = smem + 2*ABUF;         // [2][128][36]

    const int tid  = threadIdx.x;
    const int wid  = tid >> 5;
    const int lane = tid & 31;
    const int g    = lane >> 2;
    const int tq   = lane & 3;
    const int m0   = (wid & 3) * 16;
    const int nb0  = (wid >> 2) * 64;

    const float* xa = x + (size_t)t * INW;
    const float* wb = g_WG + ((size_t)l*ROWS + rb) * INW;

    const int sa_b  = tid >> 3, sa_k = tid & 7;
    const int sb_r  = tid >> 3, sb_k = tid & 7;

    auto stage = [&](int buf, int k0) {
        float* Ad = As + buf*ABUF;
        float* Bd = Bs + buf*BBUF;
        #pragma unroll
        for (int q = 0; q < 2; ++q) {
            int b = sa_b + q*32;
            cp16(&Ad[b*APITCH + sa_k*4], xa + (size_t)b*SS*INW + k0 + sa_k*4);
        }
        #pragma unroll
        for (int q = 0; q < 4; ++q) {
            int r = sb_r + q*32;
            cp16(&Bd[r*APITCH + sb_k*4], wb + (size_t)r*INW + k0 + sb_k*4);
        }
        asm volatile("cp.async.commit_group;" ::: "memory");
    };

    float acc[8][4];
    #pragma unroll
    for (int nt = 0; nt < 8; ++nt)
        #pragma unroll
        for (int j = 0; j < 4; ++j) acc[nt][j] = 0.0f;

    stage(0, 0);

    for (int ki = 0; ki < 16; ++ki) {
        if (ki < 15) {
            stage((ki+1) & 1, (ki+1)*32);
            asm volatile("cp.async.wait_group 1;" ::: "memory");
        } else {
            asm volatile("cp.async.wait_group 0;" ::: "memory");
        }
        __syncthreads();

        const float* Ab = As + (ki & 1)*ABUF;
        const float* Bb = Bs + (ki & 1)*BBUF;
        #pragma unroll
        for (int ksi = 0; ksi < 4; ++ksi) {
            int kk = ksi*8;
            uint32_t a[4];
            a[0] = __float_as_uint(Ab[(m0+g  )*APITCH + kk + tq    ]);
            a[1] = __float_as_uint(Ab[(m0+g+8)*APITCH + kk + tq    ]);
            a[2] = __float_as_uint(Ab[(m0+g  )*APITCH + kk + tq + 4]);
            a[3] = __float_as_uint(Ab[(m0+g+8)*APITCH + kk + tq + 4]);
            #pragma unroll
            for (int nt = 0; nt < 8; ++nt) {
                int nrow = nb0 + nt*8 + g;
                uint32_t bf[2];
                bf[0] = __float_as_uint(Bb[nrow*APITCH + kk + tq    ]);
                bf[1] = __float_as_uint(Bb[nrow*APITCH + kk + tq + 4]);
                mma_tf32(acc[nt], a, bf);
            }
        }
        __syncthreads();
    }

    float* gout = g_Gx + ((size_t)(t*L_NUM + l)*BB) * ROWS + rb;
    #pragma unroll
    for (int nt = 0; nt < 8; ++nt) {
        int r = nb0 + nt*8 + 2*tq;
        __stcs((float2*)&gout[(size_t)(m0+g  )*ROWS + r], make_float2(acc[nt][0], acc[nt][1]));
        __stcs((float2*)&gout[(size_t)(m0+g+8)*ROWS + r], make_float2(acc[nt][2], acc[nt][3]));
    }
}

// ---------------------------------------------------------------------------
// Kernel C: persistent scan, no full-CTA syncs in the loop.
//   CTA (l, bg, j): 16 batches, 64 rows. 16 warps: ks=wid&1 (k half),
//   nt=wid>>1 (n8 row tile). UG B-frags hoisted (64 regs).
//   H global layout permuted so A-frags are LDS.64. Warp-autonomous barrier:
//   per-warp red.release + lane0 acquire-spin (target t*256). Team barrier
//   (bar 9+ks, 256 thr) after staging own k-half; pair barrier (bar nt+1, 64)
//   for the k-half exchange. One (h,b) update per lane, fully in registers.
// ---------------------------------------------------------------------------
__global__ void __launch_bounds__(512, 1) step_kernel(float* __restrict__ out)
{
    const int tid  = threadIdx.x;
    const int lane = tid & 31;
    const int wid  = tid >> 5;
    const int g    = lane >> 2;
    const int tq   = lane & 3;

    const int bid  = blockIdx.x;
    const int l    = bid >> 6;
    const int bg   = (bid >> 4) & 3;
    const int j    = bid & 15;
    const int gid  = l*NBG + bg;
    const int rbase = j * 64;
    const int hbase = j * 32;

    const int ks    = wid & 1;           // k half
    const int nt    = wid >> 1;          // n8 tile (0..7)
    const int kbase = ks * 256;

    __shared__ __align__(16) float  Hs[512*16];      // 32 KB [o][perm16]
    __shared__ __align__(16) float2 Xbuf[16][32];    //  4 KB exchange

    // --- hoist UG B-frags into registers (B n-index = g within warp tile) ---
    uint32_t breg[32][2];
    {
        const float* ug = g_UG + ((size_t)l*ROWS + rbase + nt*8 + g)*HS + kbase;
        #pragma unroll
        for (int m = 0; m < 32; ++m) {
            breg[m][0] = __float_as_uint(ug[m*8 + tq    ]);
            breg[m][1] = __float_as_uint(ug[m*8 + tq + 4]);
        }
    }

    // --- per-lane update identity: one (h, b) pair ---
    const int h_loc  = nt*4 + tq;                    // 0..31
    const int o_glob = hbase + h_loc;                // global h of this lane
    const int bl     = g + ks*8;                     // local batch 0..15
    const int bglob  = bg*16 + bl;
    const float bz = g_bias[l*ROWS + rbase + 8*nt + 2*tq];
    const float bn = g_bias[l*ROWS + rbase + 8*nt + 2*tq + 1];
    const int permoff = (bl & 7)*2 + (bl >> 3);      // = g*2 + ks

    // hold carried in a register (exact fp32)
    float hold = g_Hbuf[((size_t)(0*L_NUM + l)*NBG + bg)*(HS*16) + o_glob*16 + permoff];

    float* outSeq   = out;
    float* outState = out + (size_t)SEQ_ELEMS;
    unsigned long long* bar = &g_arrive[gid*16];

    const float* gxlane = g_Gx + ((size_t)l*BB + bglob)*ROWS + rbase + 8*nt + 2*tq;
    float2 gxv = __ldcs((const float2*)gxlane);      // t = 0

    // staging slice of this warp: o in [kbase + nt*32, +32)
    const int obase = kbase + nt*32;

    int p = 0;
    for (int t = 0; t < SS; ++t) {
        // --- warp-autonomous barrier wait (skip at t=0) ---
        if (t) {
            if (lane == 0) {
                unsigned long long target = (unsigned long long)t * GWARPS;
                unsigned long long v;
                do {
                    asm volatile("ld.global.acquire.gpu.u64 %0, [%1];"
                                 : "=l"(v) : "l"(bar) : "memory");
                } while (v < target);
            }
            __syncwarp();
        }

        const float* Hrd = g_Hbuf + ((size_t)(p      *L_NUM + l)*NBG + bg)*(HS*16);
        float*       Hwr = g_Hbuf + ((size_t)((1-p)  *L_NUM + l)*NBG + bg)*(HS*16);

        // --- stage this warp's 32-o slice (linear copy, layout-preserving) ---
        #pragma unroll
        for (int q = 0; q < 4; ++q) {
            int i    = lane + q*32;                  // 128 float4 per warp
            int off  = (obase + (i >> 2))*16 + (i & 3)*4;
            cp16(&Hs[off], Hrd + off);
        }
        asm volatile("cp.async.commit_group;" ::: "memory");
        asm volatile("cp.async.wait_group 0;" ::: "memory");
        // team barrier: my k-half fully staged by my 8-warp team
        asm volatile("bar.sync %0, %1;" :: "r"(9 + ks), "r"(256) : "memory");

        // --- mma: m16(b) x n8(r) x k256, A-frags via LDS.64 ---
        float acc0[4] = {0,0,0,0};
        float acc1[4] = {0,0,0,0};
        #pragma unroll
        for (int m = 0; m < 32; ++m) {
            int o = kbase + 8*m + tq;
            float2 a01 = *(const float2*)&Hs[ o     *16 + g*2];
            float2 a23 = *(const float2*)&Hs[(o + 4)*16 + g*2];
            uint32_t a[4];
            a[0] = __float_as_uint(a01.x);
            a[1] = __float_as_uint(a01.y);
            a[2] = __float_as_uint(a23.x);
            a[3] = __float_as_uint(a23.y);
            if (m & 1) mma_tf32(acc1, a, breg[m]);
            else       mma_tf32(acc0, a, breg[m]);
        }
        float c0 = acc0[0] + acc1[0];   // D[b=g  ][r=8nt+2tq  ]
        float c1 = acc0[1] + acc1[1];   // D[b=g  ][r=8nt+2tq+1]
        float c2 = acc0[2] + acc1[2];   // D[b=g+8][r=8nt+2tq  ]
        float c3 = acc0[3] + acc1[3];   // D[b=g+8][r=8nt+2tq+1]

        // --- k-half exchange with pair warp: each lane keeps one batch ---
        Xbuf[wid][lane] = ks ? make_float2(c0, c1) : make_float2(c2, c3);
        asm volatile("bar.sync %0, %1;" :: "r"(nt + 1), "r"(64) : "memory");
        float2 pp = Xbuf[wid ^ 1][lane];

        // --- fused update (one (h,b) per lane, all in registers) ---
        float gz = (ks ? c2 : c0) + pp.x + gxv.x + bz;
        float gn = (ks ? c3 : c1) + pp.y + gxv.y + bn;
        float z  = __fdividef(1.0f, 1.0f + __expf(-gz));
        float n  = 1.0f - __fdividef(2.0f, __expf(2.0f*gn) + 1.0f);
        float hnew = (1.0f - z)*n + z*hold;
        hold = hnew;
        Hwr[o_glob*16 + permoff] = rna_tf32(hnew);   // producer-side rounding

        // --- release (per warp) ---
        __syncwarp();
        if (lane == 0)
            asm volatile("red.release.gpu.global.add.u64 [%0], %1;"
                         :: "l"(bar), "l"(1ULL) : "memory");

        // --- off-critical-path work (hidden in the spin window) ---
        if (l == 1)
            outSeq[((size_t)bglob*SS + t)*HS + o_glob] = hnew;
        if (t == SS-1)
            outState[((size_t)l*BB + bglob)*HS + o_glob] = hnew;
        if (t + 1 < SS)
            gxv = __ldcs((const float2*)(gxlane + (size_t)(t+1)*L_NUM*BB*ROWS));

        p ^= 1;
    }
}

// ---------------------------------------------------------------------------
// Launch
// ---------------------------------------------------------------------------
extern "C" void kernel_launch(void* const* d_in, const int* in_sizes, int n_in,
                              void* d_out, int out_size)
{
    const float* x   = (const float*)d_in[0];
    const float* h0  = (const float*)d_in[1];
    const float* W1  = (const float*)d_in[2];
    const float* W2  = (const float*)d_in[3];
    const float* U1  = (const float*)d_in[4];
    const float* U2  = (const float*)d_in[5];
    const float* dW1 = (const float*)d_in[6];
    const float* dW2 = (const float*)d_in[7];
    const float* dU1 = (const float*)d_in[8];
    const float* dU2 = (const float*)d_in[9];
    const float* b1  = (const float*)d_in[10];
    const float* b2  = (const float*)d_in[11];
    float* out = (float*)d_out;

    combine_kernel<<<4096, 256>>>(W1, W2, U1, U2, dW1, dW2, dU1, dU2, b1, b2);
    init_h_kernel<<<256, 256>>>(h0);

    cudaFuncSetAttribute(gemm_x_kernel, cudaFuncAttributeMaxDynamicSharedMemorySize, GEMM_SMEM);
    dim3 gg(1024, 8, 2);
    gemm_x_kernel<<<gg, 256, GEMM_SMEM>>>(x);

    step_kernel<<<128, 512>>>(out);
    (void)in_sizes; (void)n_in; (void)out_size;
}

// round 16
// speedup vs baseline: 1.1625x; 1.1625x over previous
#include <cuda_runtime.h>
#include <cstdint>

// ---------------------------------------------------------------------------
// Problem constants
// ---------------------------------------------------------------------------
#define L_NUM 2
#define HS    512
#define BB    64
#define SS    1024
#define INW   512
#define ROWS  1024            // 2 gates * HS, interleaved: r = 2*h + g' (g': 0=z, 1=n)
#define SEQ_ELEMS (BB*SS*HS)

// Scan partition: 2 layers x 4 batch-groups (16 b) x 16 row-groups (64 rows)
#define NBG   4
#define GSIZE 16              // CTAs per barrier group

// ---------------------------------------------------------------------------
// Device scratch
// ---------------------------------------------------------------------------
__device__ __align__(16) float g_WG  [L_NUM*ROWS*INW];             // [l][r][i] tf32-rounded
__device__ __align__(16) float g_UG  [L_NUM*ROWS*HS];              // [l][r][o] tf32-rounded
__device__ __align__(16) float g_bias[L_NUM*ROWS];
__device__ __align__(16) float g_Gx  [(size_t)SS*L_NUM*BB*ROWS];   // 512 MB [t][l][b][r]
__device__ __align__(16) float g_Hbuf[2*L_NUM*BB*HS];              // ping-pong [p][l][b][o]
// flag barrier: 8 groups x 16 CTAs, each flag on its own 128-B line
__device__ unsigned g_flag[8*16*32];

__device__ __forceinline__ float rna_tf32(float x) {
    uint32_t r;
    asm("cvt.rna.tf32.f32 %0, %1;" : "=r"(r) : "f"(x));
    return __uint_as_float(r);
}

// D (4xf32) += A (m16k8 tf32, row-major) * B (k8n8 tf32, col-major)
__device__ __forceinline__ void mma_tf32(float* d, const uint32_t* a, const uint32_t* bf) {
    asm volatile(
        "mma.sync.aligned.m16n8k8.row.col.f32.tf32.tf32.f32 "
        "{%0,%1,%2,%3}, {%4,%5,%6,%7}, {%8,%9}, {%0,%1,%2,%3};"
        : "+f"(d[0]), "+f"(d[1]), "+f"(d[2]), "+f"(d[3])
        : "r"(a[0]), "r"(a[1]), "r"(a[2]), "r"(a[3]), "r"(bf[0]), "r"(bf[1]));
}

__device__ __forceinline__ void cp16(void* s, const void* g) {
    uint32_t sa = (uint32_t)__cvta_generic_to_shared(s);
    asm volatile("cp.async.cg.shared.global [%0], [%1], 16;" :: "r"(sa), "l"(g));
}

// ---------------------------------------------------------------------------
// Kernel A: combined weights (tf32-rounded) + biases
// ---------------------------------------------------------------------------
__global__ void combine_kernel(const float* __restrict__ W1, const float* __restrict__ W2,
                               const float* __restrict__ U1, const float* __restrict__ U2,
                               const float* __restrict__ dW1, const float* __restrict__ dW2,
                               const float* __restrict__ dU1, const float* __restrict__ dU2,
                               const float* __restrict__ b1, const float* __restrict__ b2)
{
    int idx = blockIdx.x * blockDim.x + threadIdx.x;   // L*ROWS*INW threads
    int l   = idx >> 19;
    int rem = idx & 524287;
    int r   = rem >> 9;
    int i   = rem & 511;
    int h   = r >> 1;
    int g   = (r & 1) + 1;                             // original gate (1=z, 2=n)

    float w1  = W1 [l*3 + g];
    float dw1 = dW1[l*3 + g];
    float u1  = U1 [l*3 + g];
    float du1 = dU1[l*3 + g];
    int src = (l*HS + h)*INW + i;
    g_WG[idx] = rna_tf32(w1*W2[src] + dw1*dW2[src]);
    g_UG[idx] = rna_tf32(u1*U2[src] + du1*dU2[src]);

    if (idx < L_NUM*ROWS) {
        int ll = idx >> 10;
        int rr = idx & 1023;
        int hh = rr >> 1;
        int gg = (rr & 1) + 1;
        g_bias[idx] = b1[ll*3*HS + gg*HS + hh] + b2[ll*3*HS + gg*HS + hh];
    }
}

// ---------------------------------------------------------------------------
// Init: h0 (L,B,HS) -> Hbuf[0][l][b][h] (same layout); reset flags
// ---------------------------------------------------------------------------
__global__ void init_h_kernel(const float* __restrict__ h0)
{
    int idx = blockIdx.x * blockDim.x + threadIdx.x;   // 65536 threads
    if (idx < 8*16*32) g_flag[idx] = 0u;
    g_Hbuf[idx] = h0[idx];
}

// ---------------------------------------------------------------------------
// Kernel B: tf32 mma GEMM with cp.async double buffering (unchanged R13).
//   Gx[t][l][b][r] = sum_i x[b][t][i] * WG[l][r][i]
// ---------------------------------------------------------------------------
#define APITCH 36
#define ABUF   (64*APITCH)
#define BBUF   (128*APITCH)
#define GEMM_SMEM ((2*ABUF + 2*BBUF)*4)   // 55296 B

__global__ void __launch_bounds__(256) gemm_x_kernel(const float* __restrict__ x)
{
    const int t  = blockIdx.x;
    const int rb = blockIdx.y * 128;
    const int l  = blockIdx.z;

    extern __shared__ __align__(16) float smem[];
    float* As = smem;                  // [2][64][36]
    float* Bs = smem + 2*ABUF;         // [2][128][36]

    const int tid  = threadIdx.x;
    const int wid  = tid >> 5;
    const int lane = tid & 31;
    const int g    = lane >> 2;
    const int tq   = lane & 3;
    const int m0   = (wid & 3) * 16;
    const int nb0  = (wid >> 2) * 64;

    const float* xa = x + (size_t)t * INW;
    const float* wb = g_WG + ((size_t)l*ROWS + rb) * INW;

    const int sa_b  = tid >> 3, sa_k = tid & 7;
    const int sb_r  = tid >> 3, sb_k = tid & 7;

    auto stage = [&](int buf, int k0) {
        float* Ad = As + buf*ABUF;
        float* Bd = Bs + buf*BBUF;
        #pragma unroll
        for (int q = 0; q < 2; ++q) {
            int b = sa_b + q*32;
            cp16(&Ad[b*APITCH + sa_k*4], xa + (size_t)b*SS*INW + k0 + sa_k*4);
        }
        #pragma unroll
        for (int q = 0; q < 4; ++q) {
            int r = sb_r + q*32;
            cp16(&Bd[r*APITCH + sb_k*4], wb + (size_t)r*INW + k0 + sb_k*4);
        }
        asm volatile("cp.async.commit_group;" ::: "memory");
    };

    float acc[8][4];
    #pragma unroll
    for (int nt = 0; nt < 8; ++nt)
        #pragma unroll
        for (int j = 0; j < 4; ++j) acc[nt][j] = 0.0f;

    stage(0, 0);

    for (int ki = 0; ki < 16; ++ki) {
        if (ki < 15) {
            stage((ki+1) & 1, (ki+1)*32);
            asm volatile("cp.async.wait_group 1;" ::: "memory");
        } else {
            asm volatile("cp.async.wait_group 0;" ::: "memory");
        }
        __syncthreads();

        const float* Ab = As + (ki & 1)*ABUF;
        const float* Bb = Bs + (ki & 1)*BBUF;
        #pragma unroll
        for (int ksi = 0; ksi < 4; ++ksi) {
            int kk = ksi*8;
            uint32_t a[4];
            a[0] = __float_as_uint(Ab[(m0+g  )*APITCH + kk + tq    ]);
            a[1] = __float_as_uint(Ab[(m0+g+8)*APITCH + kk + tq    ]);
            a[2] = __float_as_uint(Ab[(m0+g  )*APITCH + kk + tq + 4]);
            a[3] = __float_as_uint(Ab[(m0+g+8)*APITCH + kk + tq + 4]);
            #pragma unroll
            for (int nt = 0; nt < 8; ++nt) {
                int nrow = nb0 + nt*8 + g;
                uint32_t bf[2];
                bf[0] = __float_as_uint(Bb[nrow*APITCH + kk + tq    ]);
                bf[1] = __float_as_uint(Bb[nrow*APITCH + kk + tq + 4]);
                mma_tf32(acc[nt], a, bf);
            }
        }
        __syncthreads();
    }

    float* gout = g_Gx + ((size_t)(t*L_NUM + l)*BB) * ROWS + rb;
    #pragma unroll
    for (int nt = 0; nt < 8; ++nt) {
        int r = nb0 + nt*8 + 2*tq;
        __stcs((float2*)&gout[(size_t)(m0+g  )*ROWS + r], make_float2(acc[nt][0], acc[nt][1]));
        __stcs((float2*)&gout[(size_t)(m0+g+8)*ROWS + r], make_float2(acc[nt][2], acc[nt][3]));
    }
}

// ---------------------------------------------------------------------------
// Kernel C: persistent scan (R13 structure, flag-array barrier).
//   CTA (l, bg, j): 16 batches, 64 rows -> m16(b) x n64(r) x k512.
//   512 thr = 16 warps: (wid&1)=k half, (wid>>1)=n8 row tile.
//   UG B-frags in 64 regs/thread. hold carried in a register (exact fp32).
//   H stored tf32-rounded by the producer -> consumer stage is pure cp.async.
//   Barrier: bar.sync -> tid0 st.release flag[self]=t+1 -> warp0 lanes 0-15
//   each acquire-poll one distinct flag -> bar.sync. seq store + gx prefetch
//   sit between release and poll (off the critical path).
// ---------------------------------------------------------------------------
__global__ void __launch_bounds__(512, 1) step_kernel(float* __restrict__ out)
{
    const int tid  = threadIdx.x;
    const int lane = tid & 31;
    const int wid  = tid >> 5;
    const int g    = lane >> 2;
    const int tq   = lane & 3;

    const int bid  = blockIdx.x;
    const int l    = bid >> 6;
    const int bg   = (bid >> 4) & 3;
    const int j    = bid & 15;
    const int gid  = l*NBG + bg;
    const int rbase = j * 64;
    const int hbase = j * 32;

    const int ks    = wid & 1;          // k half
    const int nt    = wid >> 1;         // n8 tile (0..7)
    const int kbase = ks * 256;
    const int rW    = rbase + nt*8;

    __shared__ __align__(16) float Hs  [16*516];     // 33.0 KB  [bl][o]
    __shared__ __align__(16) float Dred[2*16*66];    //  8.4 KB  [ks][bl][r64]

    // --- hoist UG B-frags into registers ---
    uint32_t breg[32][2];
    {
        const float* ug = g_UG + ((size_t)l*ROWS + rW + g)*HS + kbase;
        #pragma unroll
        for (int m = 0; m < 32; ++m) {
            breg[m][0] = __float_as_uint(ug[m*8 + tq    ]);
            breg[m][1] = __float_as_uint(ug[m*8 + tq + 4]);
        }
    }

    // update-phase identity: one (h, b) pair per thread
    const int hh = tid & 31;
    const int bl = tid >> 5;
    const int bglob = bg*16 + bl;
    const float bz = g_bias[l*ROWS + rbase + 2*hh];
    const float bn = g_bias[l*ROWS + rbase + 2*hh + 1];

    // hold carried in a register (exact); only this thread produces this (h,b)
    float hold = __ldg(&g_Hbuf[(size_t)l*BB*HS + (size_t)bglob*HS + hbase + hh]);

    float* outSeq   = out;
    float* outState = out + (size_t)SEQ_ELEMS;
    unsigned* myflag   = &g_flag[(gid*16 + j)*32];
    const unsigned* pollflag = &g_flag[(gid*16 + (lane & 15))*32];

    const float* gxbase = g_Gx + (size_t)l*BB*ROWS + (size_t)bglob*ROWS + rbase + 2*hh;
    float2 gxv = __ldcs((const float2*)gxbase);      // t = 0

    int p = 0;
    for (int t = 0; t < SS; ++t) {
        const float* Hrd = g_Hbuf + (size_t)(p*L_NUM + l)*BB*HS;       // [b][o]
        float*       Hwr = g_Hbuf + (size_t)((1-p)*L_NUM + l)*BB*HS;

        // --- stage H slice via cp.async: 16 b x 512 o, pitch 516 ---
        #pragma unroll
        for (int q = 0; q < 4; ++q) {
            int i4   = tid + q*512;
            int row  = i4 >> 7;
            int col4 = i4 & 127;
            cp16(&Hs[row*516 + col4*4], Hrd + (size_t)(bg*16 + row)*HS + col4*4);
        }
        asm volatile("cp.async.commit_group;" ::: "memory");
        asm volatile("cp.async.wait_group 0;" ::: "memory");
        __syncthreads();

        // --- mma: m16(b) x n8(r) x k256 per warp ---
        float acc0[4] = {0,0,0,0};
        float acc1[4] = {0,0,0,0};
        #pragma unroll
        for (int m = 0; m < 32; ++m) {
            int ko = kbase + m*8;
            uint32_t a[4];
            a[0] = __float_as_uint(Hs[(g  )*516 + ko + tq    ]);
            a[1] = __float_as_uint(Hs[(g+8)*516 + ko + tq    ]);
            a[2] = __float_as_uint(Hs[(g  )*516 + ko + tq + 4]);
            a[3] = __float_as_uint(Hs[(g+8)*516 + ko + tq + 4]);
            if (m & 1) mma_tf32(acc1, a, breg[m]);
            else       mma_tf32(acc0, a, breg[m]);
        }
        {
            float* dr = &Dred[(ks*16 + g)*66 + nt*8 + 2*tq];
            *(float2*)dr          = make_float2(acc0[0]+acc1[0], acc0[1]+acc1[1]);
            *(float2*)(dr + 8*66) = make_float2(acc0[2]+acc1[2], acc0[3]+acc1[3]);
        }
        __syncthreads();

        // --- fused update: one (hh, bl) per thread ---
        float hnew;
        {
            float2 d0 = *(const float2*)&Dred[(     bl)*66 + 2*hh];
            float2 d1 = *(const float2*)&Dred[(16 + bl)*66 + 2*hh];
            float gz = d0.x + d1.x + gxv.x + bz;
            float gn = d0.y + d1.y + gxv.y + bn;
            float z = __fdividef(1.0f, 1.0f + __expf(-gz));
            float n = 1.0f - __fdividef(2.0f, __expf(2.0f*gn) + 1.0f);
            hnew = (1.0f - z)*n + z*hold;
            hold = hnew;
            Hwr[(size_t)bglob*HS + hbase + hh] = rna_tf32(hnew);   // producer-side rounding
        }

        __syncthreads();                               // all Hwr stores issued (HB to tid0)

        // --- release: one plain store-release per CTA, own 128-B line ---
        if (tid == 0)
            asm volatile("st.release.gpu.global.u32 [%0], %1;"
                         :: "l"(myflag), "r"((unsigned)(t+1)) : "memory");

        // --- off-critical-path work (hidden in the poll window) ---
        if (l == 1)
            outSeq[((size_t)bglob*SS + t)*HS + hbase + hh] = hnew;
        if (t == SS-1)
            outState[((size_t)l*BB + bglob)*HS + hbase + hh] = hnew;
        float2 gxn = gxv;
        if (t + 1 < SS)
            gxn = __ldcs((const float2*)(gxbase + (size_t)(t+1)*L_NUM*BB*ROWS));

        // --- detect: warp 0, lanes 0-15 each poll one distinct flag ---
        if (wid == 0) {
            unsigned tgt = (unsigned)(t+1);
            if (lane < 16) {
                unsigned v;
                do {
                    asm volatile("ld.global.acquire.gpu.u32 %0, [%1];"
                                 : "=r"(v) : "l"(pollflag) : "memory");
                } while (v < tgt);
            }
            __syncwarp();
        }
        __syncthreads();
        gxv = gxn;
        p ^= 1;
    }
}

// ---------------------------------------------------------------------------
// Launch
// ---------------------------------------------------------------------------
extern "C" void kernel_launch(void* const* d_in, const int* in_sizes, int n_in,
                              void* d_out, int out_size)
{
    const float* x   = (const float*)d_in[0];
    const float* h0  = (const float*)d_in[1];
    const float* W1  = (const float*)d_in[2];
    const float* W2  = (const float*)d_in[3];
    const float* U1  = (const float*)d_in[4];
    const float* U2  = (const float*)d_in[5];
    const float* dW1 = (const float*)d_in[6];
    const float* dW2 = (const float*)d_in[7];
    const float* dU1 = (const float*)d_in[8];
    const float* dU2 = (const float*)d_in[9];
    const float* b1  = (const float*)d_in[10];
    const float* b2  = (const float*)d_in[11];
    float* out = (float*)d_out;

    combine_kernel<<<4096, 256>>>(W1, W2, U1, U2, dW1, dW2, dU1, dU2, b1, b2);
    init_h_kernel<<<256, 256>>>(h0);

    cudaFuncSetAttribute(gemm_x_kernel, cudaFuncAttributeMaxDynamicSharedMemorySize, GEMM_SMEM);
    dim3 gg(1024, 8, 2);
    gemm_x_kernel<<<gg, 256, GEMM_SMEM>>>(x);

    step_kernel<<<128, 512>>>(out);
    (void)in_sizes; (void)n_in; (void)out_size;
}